// round 7
// baseline (speedup 1.0000x reference)
#include <cuda_runtime.h>
#include <cuda_fp16.h>
#include <cstdint>

// out = elu(input @ W)  [reference's softmax(eye-mask) == Identity exactly]
// fp32 GEMM M=8192 N=2048 K=2048, single fp16 term on mma.sync.m16n8k16
// (measured rel_err 3.0e-4 < 1e-3).
// R6: CTA 128x128, 4 warps, warp tile 64x64 (smem reads 192->96KB/chunk),
//     4-stage cp.async, 1024 CTAs (6.92 waves -> ~1% tail vs 13.5%).

#define GM 8192
#define GN 2048
#define GK 2048

#define BM 128
#define BN 128
#define BK 64
#define NTHREADS 128
#define NCHUNK (GK / BK)   // 32

// ---------------- scratch (fp16 operands) ----------------
__device__ __half g_Ah[(size_t)GM * GK];
__device__ __half g_Bh[(size_t)GN * GK];   // W^T, K-major rows

// ---------------- smem stage layout ----------------
// per stage: Ah 16K | Bh 16K   (rows of 128B, SW128)
#define SA 0
#define SB 16384
#define STAGE_BYTES 32768
#define NSTAGE 4
#define SMEM_TOTAL (NSTAGE * STAGE_BYTES)   // 131072 -> occ 1

#define SWZ(o) ((o) ^ (((o) >> 3) & 0x70))

__device__ __forceinline__ uint32_t smem_u32(const void* p) {
    uint32_t a;
    asm("{ .reg .u64 t; cvta.to.shared.u64 t, %1; cvt.u32.u64 %0, t; }" : "=r"(a) : "l"(p));
    return a;
}
__device__ __forceinline__ void cp16(uint32_t dst, const void* src) {
    asm volatile("cp.async.cg.shared.global [%0], [%1], 16;" :: "r"(dst), "l"(src));
}
__device__ __forceinline__ void cp_commit() {
    asm volatile("cp.async.commit_group;" ::: "memory");
}
__device__ __forceinline__ void cp_wait3() {
    asm volatile("cp.async.wait_group 3;" ::: "memory");
}
__device__ __forceinline__ void ldsm4(uint32_t addr, uint32_t& r0, uint32_t& r1,
                                      uint32_t& r2, uint32_t& r3) {
    asm volatile("ldmatrix.sync.aligned.m8n8.x4.shared.b16 {%0,%1,%2,%3}, [%4];"
                 : "=r"(r0), "=r"(r1), "=r"(r2), "=r"(r3) : "r"(addr));
}
__device__ __forceinline__ void mma16816(float& d0, float& d1, float& d2, float& d3,
                                         uint32_t a0, uint32_t a1, uint32_t a2, uint32_t a3,
                                         uint32_t b0, uint32_t b1) {
    asm volatile(
        "mma.sync.aligned.m16n8k16.row.col.f32.f16.f16.f32 "
        "{%0,%1,%2,%3}, {%4,%5,%6,%7}, {%8,%9}, {%0,%1,%2,%3};"
        : "+f"(d0), "+f"(d1), "+f"(d2), "+f"(d3)
        : "r"(a0), "r"(a1), "r"(a2), "r"(a3), "r"(b0), "r"(b1));
}
__device__ __forceinline__ float elu_f(float x) { return x > 0.0f ? x : expm1f(x); }

// ---------------- conversion kernels ----------------
__global__ __launch_bounds__(256) void conv_a_kernel(const float4* __restrict__ A) {
    size_t i = (size_t)blockIdx.x * 256 + threadIdx.x;
    float4 v = A[i];
    __half2* ph = reinterpret_cast<__half2*>(g_Ah + i * 4);
    ph[0] = __half2(__float2half(v.x), __float2half(v.y));
    ph[1] = __half2(__float2half(v.z), __float2half(v.w));
}

__global__ __launch_bounds__(256) void conv_bt_kernel(const float* __restrict__ B) {
    __shared__ float tile[32][33];
    int n0 = blockIdx.x * 32, k0 = blockIdx.y * 32;
    int tx = threadIdx.x, ty = threadIdx.y;   // block (32,8)
    #pragma unroll
    for (int j = 0; j < 32; j += 8)
        tile[ty + j][tx] = B[(size_t)(k0 + ty + j) * GN + n0 + tx];
    __syncthreads();
    #pragma unroll
    for (int j = 0; j < 32; j += 8) {
        float x = tile[tx][ty + j];
        g_Bh[(size_t)(n0 + ty + j) * GK + k0 + tx] = __float2half(x);
    }
}

// ---------------- stage fill ----------------
__device__ __forceinline__ void fill_stage(uint32_t sbase, int m0, int n0, int k0) {
    const int tid = threadIdx.x;
    const char* Ah = (const char*)g_Ah;
    const char* Bh = (const char*)g_Bh;
    // A tile: 128 rows x 128B  (1024 cp16; 8 per thread)
    #pragma unroll
    for (int i = tid; i < 1024; i += NTHREADS) {
        int r = i >> 3, c = i & 7;
        uint32_t off = SWZ((uint32_t)(r * 128 + c * 16));
        size_t go = ((size_t)(m0 + r) * GK + k0) * 2 + c * 16;
        cp16(sbase + SA + off, Ah + go);
    }
    // B tile: 128 rows x 128B
    #pragma unroll
    for (int i = tid; i < 1024; i += NTHREADS) {
        int r = i >> 3, c = i & 7;
        uint32_t off = SWZ((uint32_t)(r * 128 + c * 16));
        size_t go = ((size_t)(n0 + r) * GK + k0) * 2 + c * 16;
        cp16(sbase + SB + off, Bh + go);
    }
}

// ---------------- main GEMM kernel ----------------
__global__ __launch_bounds__(NTHREADS, 1)
void gat_mma_kernel(float* __restrict__ C) {
    extern __shared__ char smem[];
    uint32_t sb = smem_u32(smem);
    const int tid  = threadIdx.x;
    const int wid  = tid >> 5;
    const int lane = tid & 31;
    const int m0 = blockIdx.y * BM;
    const int n0 = blockIdx.x * BN;
    const int warp_m = wid & 1;    // 2 M-tiles of 64
    const int warp_n = wid >> 1;   // 2 N-tiles of 64

    float acc[4][8][4];
    #pragma unroll
    for (int i = 0; i < 4; i++)
        #pragma unroll
        for (int j = 0; j < 8; j++)
            #pragma unroll
            for (int t = 0; t < 4; t++) acc[i][j][t] = 0.0f;

    // per-lane swizzled address bases:
    // SWZ(row*128 + c) == row*128 + (c ^ ((row&7)<<4))  for c < 128
    const int a_row_l = lane & 15;
    const uint32_t a_kb = (uint32_t)((lane >> 4) << 4);
    const int b_j = lane >> 3;
    const int b_row_l = (lane & 7) + ((b_j >> 1) << 3);
    const uint32_t b_kb = (uint32_t)((b_j & 1) << 4);

    uint32_t baseA[4], xA[4];
    #pragma unroll
    for (int mt = 0; mt < 4; mt++) {
        int row = warp_m * 64 + mt * 16 + a_row_l;
        baseA[mt] = (uint32_t)(row << 7);
        xA[mt]    = (uint32_t)((row & 7) << 4);
    }
    uint32_t baseB[4], xB[4];
    #pragma unroll
    for (int np = 0; np < 4; np++) {
        int row = warp_n * 64 + np * 16 + b_row_l;
        baseB[np] = (uint32_t)(row << 7);
        xB[np]    = (uint32_t)((row & 7) << 4);
    }

    // prologue: fill 4 stages
    #pragma unroll
    for (int s = 0; s < NSTAGE; s++) {
        fill_stage(sb + (uint32_t)s * STAGE_BYTES, m0, n0, s * BK);
        cp_commit();
    }

    int stage_idx = 0;
    for (int k = 0; k < NCHUNK; k++) {
        uint32_t stage = sb + (uint32_t)stage_idx * STAGE_BYTES;
        cp_wait3();   // chunk k resident
        __syncthreads();

        #pragma unroll
        for (int ks = 0; ks < 4; ks++) {
            const uint32_t kb = (uint32_t)(ks * 32);

            // B fragments: 4 ldsm.x4 cover 8 n-tiles (warp's 64 cols)
            uint32_t bh[8][2];
            #pragma unroll
            for (int np = 0; np < 4; np++) {
                uint32_t ad = stage + SB + baseB[np] + ((kb + b_kb) ^ xB[np]);
                uint32_t r0, r1, r2, r3;
                ldsm4(ad, r0, r1, r2, r3);
                bh[np * 2 + 0][0] = r0; bh[np * 2 + 0][1] = r1;
                bh[np * 2 + 1][0] = r2; bh[np * 2 + 1][1] = r3;
            }

            // A fragments double-buffered over mt; 8 MMAs per mt
            uint32_t ah[2][4];
            {
                uint32_t ad = stage + SA + baseA[0] + ((kb + a_kb) ^ xA[0]);
                ldsm4(ad, ah[0][0], ah[0][1], ah[0][2], ah[0][3]);
            }
            #pragma unroll
            for (int mt = 0; mt < 4; mt++) {
                const int cb = mt & 1;
                if (mt < 3) {
                    const int nb = (mt + 1) & 1;
                    uint32_t ad = stage + SA + baseA[mt + 1] + ((kb + a_kb) ^ xA[mt + 1]);
                    ldsm4(ad, ah[nb][0], ah[nb][1], ah[nb][2], ah[nb][3]);
                }
                #pragma unroll
                for (int nt = 0; nt < 8; nt++)
                    mma16816(acc[mt][nt][0], acc[mt][nt][1], acc[mt][nt][2], acc[mt][nt][3],
                             ah[cb][0], ah[cb][1], ah[cb][2], ah[cb][3],
                             bh[nt][0], bh[nt][1]);
            }
        }

        __syncthreads();   // all warps done reading this stage
        if (k + NSTAGE < NCHUNK) fill_stage(stage, m0, n0, (k + NSTAGE) * BK);
        cp_commit();       // one group per iter keeps wait_group accounting
        stage_idx = (stage_idx == NSTAGE - 1) ? 0 : stage_idx + 1;
    }

    // ---------------- epilogue: fused elu, float2 stores ----------------
    const int gp  = lane >> 2;
    const int tg2 = (lane & 3) * 2;
    #pragma unroll
    for (int mt = 0; mt < 4; mt++) {
        int mrow = m0 + warp_m * 64 + mt * 16 + gp;
        #pragma unroll
        for (int nt = 0; nt < 8; nt++) {
            int ncol = n0 + warp_n * 64 + nt * 8 + tg2;
            float2 v0, v1;
            v0.x = elu_f(acc[mt][nt][0]);
            v0.y = elu_f(acc[mt][nt][1]);
            v1.x = elu_f(acc[mt][nt][2]);
            v1.y = elu_f(acc[mt][nt][3]);
            *reinterpret_cast<float2*>(C + (size_t)mrow * GN + ncol) = v0;
            *reinterpret_cast<float2*>(C + (size_t)(mrow + 8) * GN + ncol) = v1;
        }
    }
}

// ---------------- launch ----------------
extern "C" void kernel_launch(void* const* d_in, const int* in_sizes, int n_in,
                              void* d_out, int out_size) {
    const float* input = (const float*)d_in[0];   // [8192, 2048]
    const float* W     = (const float*)d_in[2];   // [2048, 2048]
    float*       out   = (float*)d_out;

    cudaFuncSetAttribute(gat_mma_kernel,
                         cudaFuncAttributeMaxDynamicSharedMemorySize, SMEM_TOTAL);

    conv_a_kernel<<<(GM * (size_t)GK) / (256 * 4), 256>>>((const float4*)input);
    conv_bt_kernel<<<dim3(GN / 32, GK / 32), dim3(32, 8)>>>(W);
    gat_mma_kernel<<<dim3(GN / BN, GM / BM), NTHREADS, SMEM_TOTAL>>>(out);
}

// round 8
// speedup vs baseline: 1.1924x; 1.1924x over previous
#include <cuda_runtime.h>
#include <cuda_fp16.h>
#include <cstdint>

// out = elu(input @ W)  [reference's softmax(eye-mask) == Identity exactly]
// fp32 GEMM M=8192 N=2048 K=2048, single fp16 term on mma.sync.m16n8k16
// (measured rel_err 3.0e-4 < 1e-3).
// R7: CTA 128x256, 8 warps (2/SMSP), warp tile 64x64 (MMA:ldsm 8:1, was 2.67:1),
//     BK=64, 3-stage cp.async. Targets the ~45us of exposed non-MMA issue work
//     identified from the R3-R6 term-count scaling series.

#define GM 8192
#define GN 2048
#define GK 2048

#define BM 128
#define BN 256
#define BK 64
#define NTHREADS 256
#define NCHUNK (GK / BK)   // 32

// ---------------- scratch (fp16 operands) ----------------
__device__ __half g_Ah[(size_t)GM * GK];
__device__ __half g_Bh[(size_t)GN * GK];   // W^T, K-major rows

// ---------------- smem stage layout ----------------
// per stage: Ah 16K | Bh 32K   (rows of 128B, SW128)
#define SA 0
#define SB 16384
#define STAGE_BYTES 49152
#define NSTAGE 3
#define SMEM_TOTAL (NSTAGE * STAGE_BYTES)   // 147456

#define SWZ(o) ((o) ^ (((o) >> 3) & 0x70))

__device__ __forceinline__ uint32_t smem_u32(const void* p) {
    uint32_t a;
    asm("{ .reg .u64 t; cvta.to.shared.u64 t, %1; cvt.u32.u64 %0, t; }" : "=r"(a) : "l"(p));
    return a;
}
__device__ __forceinline__ void cp16(uint32_t dst, const void* src) {
    asm volatile("cp.async.cg.shared.global [%0], [%1], 16;" :: "r"(dst), "l"(src));
}
__device__ __forceinline__ void cp_commit() {
    asm volatile("cp.async.commit_group;" ::: "memory");
}
__device__ __forceinline__ void cp_wait2() {
    asm volatile("cp.async.wait_group 2;" ::: "memory");
}
__device__ __forceinline__ void ldsm4(uint32_t addr, uint32_t& r0, uint32_t& r1,
                                      uint32_t& r2, uint32_t& r3) {
    asm volatile("ldmatrix.sync.aligned.m8n8.x4.shared.b16 {%0,%1,%2,%3}, [%4];"
                 : "=r"(r0), "=r"(r1), "=r"(r2), "=r"(r3) : "r"(addr));
}
__device__ __forceinline__ void mma16816(float& d0, float& d1, float& d2, float& d3,
                                         uint32_t a0, uint32_t a1, uint32_t a2, uint32_t a3,
                                         uint32_t b0, uint32_t b1) {
    asm volatile(
        "mma.sync.aligned.m16n8k16.row.col.f32.f16.f16.f32 "
        "{%0,%1,%2,%3}, {%4,%5,%6,%7}, {%8,%9}, {%0,%1,%2,%3};"
        : "+f"(d0), "+f"(d1), "+f"(d2), "+f"(d3)
        : "r"(a0), "r"(a1), "r"(a2), "r"(a3), "r"(b0), "r"(b1));
}
__device__ __forceinline__ float elu_f(float x) { return x > 0.0f ? x : expm1f(x); }

// ---------------- conversion kernels ----------------
__global__ __launch_bounds__(256) void conv_a_kernel(const float4* __restrict__ A) {
    size_t i = (size_t)blockIdx.x * 256 + threadIdx.x;
    float4 v = A[i];
    __half2* ph = reinterpret_cast<__half2*>(g_Ah + i * 4);
    ph[0] = __half2(__float2half(v.x), __float2half(v.y));
    ph[1] = __half2(__float2half(v.z), __float2half(v.w));
}

__global__ __launch_bounds__(256) void conv_bt_kernel(const float* __restrict__ B) {
    __shared__ float tile[32][33];
    int n0 = blockIdx.x * 32, k0 = blockIdx.y * 32;
    int tx = threadIdx.x, ty = threadIdx.y;   // block (32,8)
    #pragma unroll
    for (int j = 0; j < 32; j += 8)
        tile[ty + j][tx] = B[(size_t)(k0 + ty + j) * GN + n0 + tx];
    __syncthreads();
    #pragma unroll
    for (int j = 0; j < 32; j += 8) {
        float x = tile[tx][ty + j];
        g_Bh[(size_t)(n0 + ty + j) * GK + k0 + tx] = __float2half(x);
    }
}

// ---------------- stage fill ----------------
__device__ __forceinline__ void fill_stage(uint32_t sbase, int m0, int n0, int k0) {
    const int tid = threadIdx.x;
    const char* Ah = (const char*)g_Ah;
    const char* Bh = (const char*)g_Bh;
    // A tile: 128 rows x 128B  (1024 cp16, 4 per thread)
    #pragma unroll
    for (int i = tid; i < 1024; i += NTHREADS) {
        int r = i >> 3, c = i & 7;
        uint32_t off = SWZ((uint32_t)(r * 128 + c * 16));
        size_t go = ((size_t)(m0 + r) * GK + k0) * 2 + c * 16;
        cp16(sbase + SA + off, Ah + go);
    }
    // B tile: 256 rows x 128B  (2048 cp16, 8 per thread)
    #pragma unroll
    for (int i = tid; i < 2048; i += NTHREADS) {
        int r = i >> 3, c = i & 7;
        uint32_t off = SWZ((uint32_t)(r * 128 + c * 16));
        size_t go = ((size_t)(n0 + r) * GK + k0) * 2 + c * 16;
        cp16(sbase + SB + off, Bh + go);
    }
}

// ---------------- main GEMM kernel ----------------
__global__ __launch_bounds__(NTHREADS, 1)
void gat_mma_kernel(float* __restrict__ C) {
    extern __shared__ char smem[];
    uint32_t sb = smem_u32(smem);
    const int tid  = threadIdx.x;
    const int wid  = tid >> 5;
    const int lane = tid & 31;
    const int m0 = blockIdx.y * BM;
    const int n0 = blockIdx.x * BN;
    const int warp_m = wid & 1;    // 2 M-tiles of 64
    const int warp_n = wid >> 1;   // 4 N-tiles of 64

    float acc[4][8][4];
    #pragma unroll
    for (int i = 0; i < 4; i++)
        #pragma unroll
        for (int j = 0; j < 8; j++)
            #pragma unroll
            for (int t = 0; t < 4; t++) acc[i][j][t] = 0.0f;

    // per-lane swizzled address bases:
    // SWZ(row*128 + c) == row*128 + (c ^ ((row&7)<<4))  for c < 128
    const int a_row_l = lane & 15;
    const uint32_t a_kb = (uint32_t)((lane >> 4) << 4);
    const int b_j = lane >> 3;
    const int b_row_l = (lane & 7) + ((b_j >> 1) << 3);
    const uint32_t b_kb = (uint32_t)((b_j & 1) << 4);

    uint32_t baseA[4], xA[4];
    #pragma unroll
    for (int mt = 0; mt < 4; mt++) {
        int row = warp_m * 64 + mt * 16 + a_row_l;
        baseA[mt] = (uint32_t)(row << 7);
        xA[mt]    = (uint32_t)((row & 7) << 4);
    }
    uint32_t baseB[4], xB[4];
    #pragma unroll
    for (int np = 0; np < 4; np++) {
        int row = warp_n * 64 + np * 16 + b_row_l;
        baseB[np] = (uint32_t)(row << 7);
        xB[np]    = (uint32_t)((row & 7) << 4);
    }

    // prologue: fill 3 stages
    #pragma unroll
    for (int s = 0; s < NSTAGE; s++) {
        fill_stage(sb + (uint32_t)s * STAGE_BYTES, m0, n0, s * BK);
        cp_commit();
    }

    int stage_idx = 0;
    for (int k = 0; k < NCHUNK; k++) {
        uint32_t stage = sb + (uint32_t)stage_idx * STAGE_BYTES;
        cp_wait2();   // chunk k resident
        __syncthreads();

        #pragma unroll
        for (int ks = 0; ks < 4; ks++) {
            const uint32_t kb = (uint32_t)(ks * 32);

            // B fragments: 4 ldsm.x4 cover 8 n-tiles (warp's 64 cols)
            uint32_t bh[8][2];
            #pragma unroll
            for (int np = 0; np < 4; np++) {
                uint32_t ad = stage + SB + baseB[np] + ((kb + b_kb) ^ xB[np]);
                uint32_t r0, r1, r2, r3;
                ldsm4(ad, r0, r1, r2, r3);
                bh[np * 2 + 0][0] = r0; bh[np * 2 + 0][1] = r1;
                bh[np * 2 + 1][0] = r2; bh[np * 2 + 1][1] = r3;
            }

            // A fragments double-buffered over mt; 8 MMAs per mt
            uint32_t ah[2][4];
            {
                uint32_t ad = stage + SA + baseA[0] + ((kb + a_kb) ^ xA[0]);
                ldsm4(ad, ah[0][0], ah[0][1], ah[0][2], ah[0][3]);
            }
            #pragma unroll
            for (int mt = 0; mt < 4; mt++) {
                const int cb = mt & 1;
                if (mt < 3) {
                    const int nb = (mt + 1) & 1;
                    uint32_t ad = stage + SA + baseA[mt + 1] + ((kb + a_kb) ^ xA[mt + 1]);
                    ldsm4(ad, ah[nb][0], ah[nb][1], ah[nb][2], ah[nb][3]);
                }
                #pragma unroll
                for (int nt = 0; nt < 8; nt++)
                    mma16816(acc[mt][nt][0], acc[mt][nt][1], acc[mt][nt][2], acc[mt][nt][3],
                             ah[cb][0], ah[cb][1], ah[cb][2], ah[cb][3],
                             bh[nt][0], bh[nt][1]);
            }
        }

        __syncthreads();   // all warps done reading this stage
        if (k + NSTAGE < NCHUNK) fill_stage(stage, m0, n0, (k + NSTAGE) * BK);
        cp_commit();       // one group per iter keeps wait_group accounting
        stage_idx = (stage_idx == NSTAGE - 1) ? 0 : stage_idx + 1;
    }

    // ---------------- epilogue: fused elu, float2 stores ----------------
    const int gp  = lane >> 2;
    const int tg2 = (lane & 3) * 2;
    #pragma unroll
    for (int mt = 0; mt < 4; mt++) {
        int mrow = m0 + warp_m * 64 + mt * 16 + gp;
        #pragma unroll
        for (int nt = 0; nt < 8; nt++) {
            int ncol = n0 + warp_n * 64 + nt * 8 + tg2;
            float2 v0, v1;
            v0.x = elu_f(acc[mt][nt][0]);
            v0.y = elu_f(acc[mt][nt][1]);
            v1.x = elu_f(acc[mt][nt][2]);
            v1.y = elu_f(acc[mt][nt][3]);
            *reinterpret_cast<float2*>(C + (size_t)mrow * GN + ncol) = v0;
            *reinterpret_cast<float2*>(C + (size_t)(mrow + 8) * GN + ncol) = v1;
        }
    }
}

// ---------------- launch ----------------
extern "C" void kernel_launch(void* const* d_in, const int* in_sizes, int n_in,
                              void* d_out, int out_size) {
    const float* input = (const float*)d_in[0];   // [8192, 2048]
    const float* W     = (const float*)d_in[2];   // [2048, 2048]
    float*       out   = (float*)d_out;

    cudaFuncSetAttribute(gat_mma_kernel,
                         cudaFuncAttributeMaxDynamicSharedMemorySize, SMEM_TOTAL);

    conv_a_kernel<<<(GM * (size_t)GK) / (256 * 4), 256>>>((const float4*)input);
    conv_bt_kernel<<<dim3(GN / 32, GK / 32), dim3(32, 8)>>>(W);
    gat_mma_kernel<<<dim3(GN / BN, GM / BM), NTHREADS, SMEM_TOTAL>>>(out);
}

// round 9
// speedup vs baseline: 1.2995x; 1.0898x over previous
#include <cuda_runtime.h>
#include <cuda_fp16.h>
#include <cstdint>

// out = elu(input @ W)  [reference's softmax(eye-mask) == Identity exactly]
// fp32 GEMM M=8192 N=2048 K=2048, single fp16 term on mma.sync.m16n8k16
// (measured rel_err 3.0e-4 < 1e-3).
// R8: keep 16 warps (4/SMSP — empirically required: 4/SMSP 244us > 2/SMSP 256
//     > 1/SMSP 306), shrink CTA to 128x128 => 1024 CTAs = 6.92 waves (tail
//     13.5% -> ~1%). 6-stage ring of 32KB stages, 2 chunks per outer iter,
//     ONE __syncthreads per 2 chunks. A+B stay L2-resident (40MB < 126MB).

#define GM 8192
#define GN 2048
#define GK 2048

#define BM 128
#define BN 128
#define BK 64
#define NTHREADS 512
#define NCHUNK (GK / BK)   // 32
#define NOUTER (NCHUNK / 2) // 16

// ---------------- scratch (fp16 operands) ----------------
__device__ __half g_Ah[(size_t)GM * GK];
__device__ __half g_Bh[(size_t)GN * GK];   // W^T, K-major rows

// ---------------- smem stage layout ----------------
// per stage: Ah 16K | Bh 16K   (rows of 128B, SW128)
#define SA 0
#define SB 16384
#define STAGE_BYTES 32768
#define NSTAGE 6
#define SMEM_TOTAL (NSTAGE * STAGE_BYTES)   // 196608

#define SWZ(o) ((o) ^ (((o) >> 3) & 0x70))

__device__ __forceinline__ uint32_t smem_u32(const void* p) {
    uint32_t a;
    asm("{ .reg .u64 t; cvta.to.shared.u64 t, %1; cvt.u32.u64 %0, t; }" : "=r"(a) : "l"(p));
    return a;
}
__device__ __forceinline__ void cp16(uint32_t dst, const void* src) {
    asm volatile("cp.async.cg.shared.global [%0], [%1], 16;" :: "r"(dst), "l"(src));
}
__device__ __forceinline__ void cp_commit() {
    asm volatile("cp.async.commit_group;" ::: "memory");
}
__device__ __forceinline__ void cp_wait2() {
    asm volatile("cp.async.wait_group 2;" ::: "memory");
}
__device__ __forceinline__ void ldsm4(uint32_t addr, uint32_t& r0, uint32_t& r1,
                                      uint32_t& r2, uint32_t& r3) {
    asm volatile("ldmatrix.sync.aligned.m8n8.x4.shared.b16 {%0,%1,%2,%3}, [%4];"
                 : "=r"(r0), "=r"(r1), "=r"(r2), "=r"(r3) : "r"(addr));
}
__device__ __forceinline__ void mma16816(float& d0, float& d1, float& d2, float& d3,
                                         uint32_t a0, uint32_t a1, uint32_t a2, uint32_t a3,
                                         uint32_t b0, uint32_t b1) {
    asm volatile(
        "mma.sync.aligned.m16n8k16.row.col.f32.f16.f16.f32 "
        "{%0,%1,%2,%3}, {%4,%5,%6,%7}, {%8,%9}, {%0,%1,%2,%3};"
        : "+f"(d0), "+f"(d1), "+f"(d2), "+f"(d3)
        : "r"(a0), "r"(a1), "r"(a2), "r"(a3), "r"(b0), "r"(b1));
}
__device__ __forceinline__ float elu_f(float x) { return x > 0.0f ? x : expm1f(x); }

// ---------------- conversion kernels ----------------
__global__ __launch_bounds__(256) void conv_a_kernel(const float4* __restrict__ A) {
    size_t base = (size_t)blockIdx.x * 1024 + threadIdx.x;
    #pragma unroll
    for (int i = 0; i < 4; i++) {
        size_t idx = base + (size_t)i * 256;
        float4 v = A[idx];
        __half2* ph = reinterpret_cast<__half2*>(g_Ah + idx * 4);
        ph[0] = __half2(__float2half(v.x), __float2half(v.y));
        ph[1] = __half2(__float2half(v.z), __float2half(v.w));
    }
}

__global__ __launch_bounds__(256) void conv_bt_kernel(const float* __restrict__ B) {
    __shared__ float tile[32][33];
    int n0 = blockIdx.x * 32, k0 = blockIdx.y * 32;
    int tx = threadIdx.x, ty = threadIdx.y;   // block (32,8)
    #pragma unroll
    for (int j = 0; j < 32; j += 8)
        tile[ty + j][tx] = B[(size_t)(k0 + ty + j) * GN + n0 + tx];
    __syncthreads();
    #pragma unroll
    for (int j = 0; j < 32; j += 8) {
        float x = tile[tx][ty + j];
        g_Bh[(size_t)(n0 + ty + j) * GK + k0 + tx] = __float2half(x);
    }
}

// ---------------- stage fill (one BK=64 chunk) ----------------
__device__ __forceinline__ void fill_stage(uint32_t sbase, int m0, int n0, int k0) {
    const int tid = threadIdx.x;
    const char* Ah = (const char*)g_Ah;
    const char* Bh = (const char*)g_Bh;
    // A tile: 128 rows x 128B  (1024 cp16, 2 per thread)
    #pragma unroll
    for (int i = tid; i < 1024; i += NTHREADS) {
        int r = i >> 3, c = i & 7;
        uint32_t off = SWZ((uint32_t)(r * 128 + c * 16));
        size_t go = ((size_t)(m0 + r) * GK + k0) * 2 + c * 16;
        cp16(sbase + SA + off, Ah + go);
    }
    // B tile: 128 rows x 128B  (1024 cp16, 2 per thread)
    #pragma unroll
    for (int i = tid; i < 1024; i += NTHREADS) {
        int r = i >> 3, c = i & 7;
        uint32_t off = SWZ((uint32_t)(r * 128 + c * 16));
        size_t go = ((size_t)(n0 + r) * GK + k0) * 2 + c * 16;
        cp16(sbase + SB + off, Bh + go);
    }
}

// ---------------- main GEMM kernel ----------------
__global__ __launch_bounds__(NTHREADS, 1)
void gat_mma_kernel(float* __restrict__ C) {
    extern __shared__ char smem[];
    uint32_t sb = smem_u32(smem);
    const int tid  = threadIdx.x;
    const int wid  = tid >> 5;
    const int lane = tid & 31;
    const int m0 = blockIdx.y * BM;
    const int n0 = blockIdx.x * BN;
    const int warp_m = wid & 3;    // 4 M-tiles of 32
    const int warp_n = wid >> 2;   // 4 N-tiles of 32

    float acc[2][4][4];
    #pragma unroll
    for (int i = 0; i < 2; i++)
        #pragma unroll
        for (int j = 0; j < 4; j++)
            #pragma unroll
            for (int t = 0; t < 4; t++) acc[i][j][t] = 0.0f;

    // per-lane swizzled address bases:
    // SWZ(row*128 + c) == row*128 + (c ^ ((row&7)<<4))  for c < 128
    const int a_row_l = lane & 15;
    const uint32_t a_kb = (uint32_t)((lane >> 4) << 4);
    const int b_j = lane >> 3;
    const int b_row_l = (lane & 7) + ((b_j >> 1) << 3);
    const uint32_t b_kb = (uint32_t)((b_j & 1) << 4);

    uint32_t baseA[2], xA[2];
    #pragma unroll
    for (int mt = 0; mt < 2; mt++) {
        int row = warp_m * 32 + mt * 16 + a_row_l;
        baseA[mt] = (uint32_t)(row << 7);
        xA[mt]    = (uint32_t)((row & 7) << 4);
    }
    uint32_t baseB[2], xB[2];
    #pragma unroll
    for (int np = 0; np < 2; np++) {
        int row = warp_n * 32 + np * 16 + b_row_l;
        baseB[np] = (uint32_t)(row << 7);
        xB[np]    = (uint32_t)((row & 7) << 4);
    }

    // prologue: fill 4 stages (chunks 0..3), one commit group per stage
    #pragma unroll
    for (int s = 0; s < 4; s++) {
        fill_stage(sb + (uint32_t)s * STAGE_BYTES, m0, n0, s * BK);
        cp_commit();
    }

    for (int o = 0; o < NOUTER; o++) {
        const int c0 = 2 * o;              // first chunk this iter
        cp_wait2();                        // chunks c0, c0+1 resident
        __syncthreads();                   // writes visible to all warps

        #pragma unroll
        for (int half = 0; half < 2; half++) {
            uint32_t stage = sb + (uint32_t)(((c0 + half) % NSTAGE)) * STAGE_BYTES;
            #pragma unroll
            for (int ks = 0; ks < 4; ks++) {
                const uint32_t kb = (uint32_t)(ks * 32);
                // B fragments: 2 ldsm.x4 cover 4 n-tiles
                uint32_t bh[4][2];
                #pragma unroll
                for (int np = 0; np < 2; np++) {
                    uint32_t ad = stage + SB + baseB[np] + ((kb + b_kb) ^ xB[np]);
                    uint32_t r0, r1, r2, r3;
                    ldsm4(ad, r0, r1, r2, r3);
                    bh[np * 2 + 0][0] = r0; bh[np * 2 + 0][1] = r1;
                    bh[np * 2 + 1][0] = r2; bh[np * 2 + 1][1] = r3;
                }
                // A fragments: 2 ldsm.x4 (2 m-tiles)
                uint32_t ah[2][4];
                #pragma unroll
                for (int mt = 0; mt < 2; mt++) {
                    uint32_t ad = stage + SA + baseA[mt] + ((kb + a_kb) ^ xA[mt]);
                    ldsm4(ad, ah[mt][0], ah[mt][1], ah[mt][2], ah[mt][3]);
                }
                #pragma unroll
                for (int mt = 0; mt < 2; mt++)
                    #pragma unroll
                    for (int nt = 0; nt < 4; nt++)
                        mma16816(acc[mt][nt][0], acc[mt][nt][1], acc[mt][nt][2], acc[mt][nt][3],
                                 ah[mt][0], ah[mt][1], ah[mt][2], ah[mt][3],
                                 bh[nt][0], bh[nt][1]);
            }
        }

        // Refill the two stages consumed two iterations ago with chunks c0+4,
        // c0+5. Safe without another sync: every warp passed this iteration's
        // top sync only after finishing the previous iteration's reads of
        // exactly these ring slots.
        #pragma unroll
        for (int half = 0; half < 2; half++) {
            int kc = c0 + 4 + half;
            if (kc < NCHUNK) {
                uint32_t stage = sb + (uint32_t)((kc % NSTAGE)) * STAGE_BYTES;
                fill_stage(stage, m0, n0, kc * BK);
            }
            cp_commit();   // empty groups keep wait_group accounting symmetric
        }
    }

    // ---------------- epilogue: fused elu, float2 stores ----------------
    const int gp  = lane >> 2;
    const int tg2 = (lane & 3) * 2;
    #pragma unroll
    for (int mt = 0; mt < 2; mt++) {
        int mrow = m0 + warp_m * 32 + mt * 16 + gp;
        #pragma unroll
        for (int nt = 0; nt < 4; nt++) {
            int ncol = n0 + warp_n * 32 + nt * 8 + tg2;
            float2 v0, v1;
            v0.x = elu_f(acc[mt][nt][0]);
            v0.y = elu_f(acc[mt][nt][1]);
            v1.x = elu_f(acc[mt][nt][2]);
            v1.y = elu_f(acc[mt][nt][3]);
            *reinterpret_cast<float2*>(C + (size_t)mrow * GN + ncol) = v0;
            *reinterpret_cast<float2*>(C + (size_t)(mrow + 8) * GN + ncol) = v1;
        }
    }
}

// ---------------- launch ----------------
extern "C" void kernel_launch(void* const* d_in, const int* in_sizes, int n_in,
                              void* d_out, int out_size) {
    const float* input = (const float*)d_in[0];   // [8192, 2048]
    const float* W     = (const float*)d_in[2];   // [2048, 2048]
    float*       out   = (float*)d_out;

    cudaFuncSetAttribute(gat_mma_kernel,
                         cudaFuncAttributeMaxDynamicSharedMemorySize, SMEM_TOTAL);

    conv_a_kernel<<<(GM * (size_t)GK) / (256 * 4 * 4), 256>>>((const float4*)input);
    conv_bt_kernel<<<dim3(GN / 32, GK / 32), dim3(32, 8)>>>(W);
    gat_mma_kernel<<<dim3(GN / BN, GM / BM), NTHREADS, SMEM_TOTAL>>>(out);
}

// round 10
// speedup vs baseline: 1.4819x; 1.1404x over previous
#include <cuda_runtime.h>
#include <cuda_fp16.h>
#include <cstdint>

// out = elu(input @ W)  [reference's softmax(eye-mask) == Identity exactly]
// fp32 GEMM M=8192 N=2048 K=2048, single fp16 term on mma.sync.m16n8k16
// (measured rel_err 3.0e-4 < 1e-3).
// R9: occupancy-2. CTA 128x128, 8 warps (warp tile 64x32), 3-stage (96KB/CTA),
//     __launch_bounds__(256,2) -> 2 CTAs/SM = 4 warps/SMSP split across two
//     async CTAs, so one CTA's cp_wait/bar/epilogue is hidden under the
//     other's MMA bursts. Targets the fixed per-chunk boundary tax that caps
//     all occ-1 one-term configs at ~320 TF/s vs the ~400 TF/s HMMA ceiling.

#define GM 8192
#define GN 2048
#define GK 2048

#define BM 128
#define BN 128
#define BK 64
#define NTHREADS 256
#define NCHUNK (GK / BK)   // 32

// ---------------- scratch (fp16 operands) ----------------
__device__ __half g_Ah[(size_t)GM * GK];
__device__ __half g_Bh[(size_t)GN * GK];   // W^T, K-major rows

// ---------------- smem stage layout ----------------
// per stage: Ah 16K | Bh 16K   (rows of 128B, SW128)
#define SA 0
#define SB 16384
#define STAGE_BYTES 32768
#define NSTAGE 3
#define SMEM_TOTAL (NSTAGE * STAGE_BYTES)   // 98304 per CTA; x2 CTAs = 192KB/SM

#define SWZ(o) ((o) ^ (((o) >> 3) & 0x70))

__device__ __forceinline__ uint32_t smem_u32(const void* p) {
    uint32_t a;
    asm("{ .reg .u64 t; cvta.to.shared.u64 t, %1; cvt.u32.u64 %0, t; }" : "=r"(a) : "l"(p));
    return a;
}
__device__ __forceinline__ void cp16(uint32_t dst, const void* src) {
    asm volatile("cp.async.cg.shared.global [%0], [%1], 16;" :: "r"(dst), "l"(src));
}
__device__ __forceinline__ void cp_commit() {
    asm volatile("cp.async.commit_group;" ::: "memory");
}
__device__ __forceinline__ void cp_wait2() {
    asm volatile("cp.async.wait_group 2;" ::: "memory");
}
__device__ __forceinline__ void ldsm4(uint32_t addr, uint32_t& r0, uint32_t& r1,
                                      uint32_t& r2, uint32_t& r3) {
    asm volatile("ldmatrix.sync.aligned.m8n8.x4.shared.b16 {%0,%1,%2,%3}, [%4];"
                 : "=r"(r0), "=r"(r1), "=r"(r2), "=r"(r3) : "r"(addr));
}
__device__ __forceinline__ void mma16816(float& d0, float& d1, float& d2, float& d3,
                                         uint32_t a0, uint32_t a1, uint32_t a2, uint32_t a3,
                                         uint32_t b0, uint32_t b1) {
    asm volatile(
        "mma.sync.aligned.m16n8k16.row.col.f32.f16.f16.f32 "
        "{%0,%1,%2,%3}, {%4,%5,%6,%7}, {%8,%9}, {%0,%1,%2,%3};"
        : "+f"(d0), "+f"(d1), "+f"(d2), "+f"(d3)
        : "r"(a0), "r"(a1), "r"(a2), "r"(a3), "r"(b0), "r"(b1));
}
__device__ __forceinline__ float elu_f(float x) { return x > 0.0f ? x : expm1f(x); }

// ---------------- conversion kernels ----------------
__global__ __launch_bounds__(256) void conv_a_kernel(const float4* __restrict__ A) {
    size_t base = (size_t)blockIdx.x * 1024 + threadIdx.x;
    #pragma unroll
    for (int i = 0; i < 4; i++) {
        size_t idx = base + (size_t)i * 256;
        float4 v = A[idx];
        __half2* ph = reinterpret_cast<__half2*>(g_Ah + idx * 4);
        ph[0] = __half2(__float2half(v.x), __float2half(v.y));
        ph[1] = __half2(__float2half(v.z), __float2half(v.w));
    }
}

__global__ __launch_bounds__(256) void conv_bt_kernel(const float* __restrict__ B) {
    __shared__ float tile[32][33];
    int n0 = blockIdx.x * 32, k0 = blockIdx.y * 32;
    int tx = threadIdx.x, ty = threadIdx.y;   // block (32,8)
    #pragma unroll
    for (int j = 0; j < 32; j += 8)
        tile[ty + j][tx] = B[(size_t)(k0 + ty + j) * GN + n0 + tx];
    __syncthreads();
    #pragma unroll
    for (int j = 0; j < 32; j += 8) {
        float x = tile[tx][ty + j];
        g_Bh[(size_t)(n0 + ty + j) * GK + k0 + tx] = __float2half(x);
    }
}

// ---------------- stage fill (one BK=64 chunk) ----------------
__device__ __forceinline__ void fill_stage(uint32_t sbase, int m0, int n0, int k0) {
    const int tid = threadIdx.x;
    const char* Ah = (const char*)g_Ah;
    const char* Bh = (const char*)g_Bh;
    // A tile: 128 rows x 128B  (1024 cp16, 4 per thread)
    #pragma unroll
    for (int i = tid; i < 1024; i += NTHREADS) {
        int r = i >> 3, c = i & 7;
        uint32_t off = SWZ((uint32_t)(r * 128 + c * 16));
        size_t go = ((size_t)(m0 + r) * GK + k0) * 2 + c * 16;
        cp16(sbase + SA + off, Ah + go);
    }
    // B tile: 128 rows x 128B  (1024 cp16, 4 per thread)
    #pragma unroll
    for (int i = tid; i < 1024; i += NTHREADS) {
        int r = i >> 3, c = i & 7;
        uint32_t off = SWZ((uint32_t)(r * 128 + c * 16));
        size_t go = ((size_t)(n0 + r) * GK + k0) * 2 + c * 16;
        cp16(sbase + SB + off, Bh + go);
    }
}

// ---------------- main GEMM kernel ----------------
__global__ __launch_bounds__(NTHREADS, 2)
void gat_mma_kernel(float* __restrict__ C) {
    extern __shared__ char smem[];
    uint32_t sb = smem_u32(smem);
    const int tid  = threadIdx.x;
    const int wid  = tid >> 5;
    const int lane = tid & 31;
    const int m0 = blockIdx.y * BM;
    const int n0 = blockIdx.x * BN;
    const int warp_m = wid & 1;    // 2 M-tiles of 64
    const int warp_n = wid >> 1;   // 4 N-tiles of 32

    float acc[4][4][4];
    #pragma unroll
    for (int i = 0; i < 4; i++)
        #pragma unroll
        for (int j = 0; j < 4; j++)
            #pragma unroll
            for (int t = 0; t < 4; t++) acc[i][j][t] = 0.0f;

    // per-lane swizzled address bases:
    // SWZ(row*128 + c) == row*128 + (c ^ ((row&7)<<4))  for c < 128
    const int a_row_l = lane & 15;
    const uint32_t a_kb = (uint32_t)((lane >> 4) << 4);
    const int b_j = lane >> 3;
    const int b_row_l = (lane & 7) + ((b_j >> 1) << 3);
    const uint32_t b_kb = (uint32_t)((b_j & 1) << 4);

    uint32_t baseA[4], xA[4];
    #pragma unroll
    for (int mt = 0; mt < 4; mt++) {
        int row = warp_m * 64 + mt * 16 + a_row_l;
        baseA[mt] = (uint32_t)(row << 7);
        xA[mt]    = (uint32_t)((row & 7) << 4);
    }
    uint32_t baseB[2], xB[2];
    #pragma unroll
    for (int np = 0; np < 2; np++) {
        int row = warp_n * 32 + np * 16 + b_row_l;
        baseB[np] = (uint32_t)(row << 7);
        xB[np]    = (uint32_t)((row & 7) << 4);
    }

    // prologue: fill 3 stages
    #pragma unroll
    for (int s = 0; s < NSTAGE; s++) {
        fill_stage(sb + (uint32_t)s * STAGE_BYTES, m0, n0, s * BK);
        cp_commit();
    }

    int stage_idx = 0;
    for (int k = 0; k < NCHUNK; k++) {
        uint32_t stage = sb + (uint32_t)stage_idx * STAGE_BYTES;
        cp_wait2();   // chunk k resident
        __syncthreads();

        #pragma unroll
        for (int ks = 0; ks < 4; ks++) {
            const uint32_t kb = (uint32_t)(ks * 32);

            // B fragments: 2 ldsm.x4 cover 4 n-tiles (warp's 32 cols)
            uint32_t bh[4][2];
            #pragma unroll
            for (int np = 0; np < 2; np++) {
                uint32_t ad = stage + SB + baseB[np] + ((kb + b_kb) ^ xB[np]);
                uint32_t r0, r1, r2, r3;
                ldsm4(ad, r0, r1, r2, r3);
                bh[np * 2 + 0][0] = r0; bh[np * 2 + 0][1] = r1;
                bh[np * 2 + 1][0] = r2; bh[np * 2 + 1][1] = r3;
            }

            // A fragments double-buffered over mt; 4 MMAs per mt
            uint32_t ah[2][4];
            {
                uint32_t ad = stage + SA + baseA[0] + ((kb + a_kb) ^ xA[0]);
                ldsm4(ad, ah[0][0], ah[0][1], ah[0][2], ah[0][3]);
            }
            #pragma unroll
            for (int mt = 0; mt < 4; mt++) {
                const int cb = mt & 1;
                if (mt < 3) {
                    const int nb = (mt + 1) & 1;
                    uint32_t ad = stage + SA + baseA[mt + 1] + ((kb + a_kb) ^ xA[mt + 1]);
                    ldsm4(ad, ah[nb][0], ah[nb][1], ah[nb][2], ah[nb][3]);
                }
                #pragma unroll
                for (int nt = 0; nt < 4; nt++)
                    mma16816(acc[mt][nt][0], acc[mt][nt][1], acc[mt][nt][2], acc[mt][nt][3],
                             ah[cb][0], ah[cb][1], ah[cb][2], ah[cb][3],
                             bh[nt][0], bh[nt][1]);
            }
        }

        __syncthreads();   // all warps done reading this stage
        if (k + NSTAGE < NCHUNK) fill_stage(stage, m0, n0, (k + NSTAGE) * BK);
        cp_commit();       // one group per iter keeps wait_group accounting
        stage_idx = (stage_idx == NSTAGE - 1) ? 0 : stage_idx + 1;
    }

    // ---------------- epilogue: fused elu, float2 stores ----------------
    const int gp  = lane >> 2;
    const int tg2 = (lane & 3) * 2;
    #pragma unroll
    for (int mt = 0; mt < 4; mt++) {
        int mrow = m0 + warp_m * 64 + mt * 16 + gp;
        #pragma unroll
        for (int nt = 0; nt < 4; nt++) {
            int ncol = n0 + warp_n * 32 + nt * 8 + tg2;
            float2 v0, v1;
            v0.x = elu_f(acc[mt][nt][0]);
            v0.y = elu_f(acc[mt][nt][1]);
            v1.x = elu_f(acc[mt][nt][2]);
            v1.y = elu_f(acc[mt][nt][3]);
            *reinterpret_cast<float2*>(C + (size_t)mrow * GN + ncol) = v0;
            *reinterpret_cast<float2*>(C + (size_t)(mrow + 8) * GN + ncol) = v1;
        }
    }
}

// ---------------- launch ----------------
extern "C" void kernel_launch(void* const* d_in, const int* in_sizes, int n_in,
                              void* d_out, int out_size) {
    const float* input = (const float*)d_in[0];   // [8192, 2048]
    const float* W     = (const float*)d_in[2];   // [2048, 2048]
    float*       out   = (float*)d_out;

    cudaFuncSetAttribute(gat_mma_kernel,
                         cudaFuncAttributeMaxDynamicSharedMemorySize, SMEM_TOTAL);

    conv_a_kernel<<<(GM * (size_t)GK) / (256 * 4 * 4), 256>>>((const float4*)input);
    conv_bt_kernel<<<dim3(GN / 32, GK / 32), dim3(32, 8)>>>(W);
    gat_mma_kernel<<<dim3(GN / BN, GM / BM), NTHREADS, SMEM_TOTAL>>>(out);
}

// round 11
// speedup vs baseline: 1.4998x; 1.0121x over previous
#include <cuda_runtime.h>
#include <cuda_fp16.h>
#include <cstdint>

// out = elu(input @ W)  [reference's softmax(eye-mask) == Identity exactly]
// fp32 GEMM M=8192 N=2048 K=2048, single fp16 term on mma.sync.m16n8k16
// (measured rel_err 3.0e-4 < 1e-3).
// R10: R9 (occ-2, CTA 128x128, 8 warps, warp 64x32, 3-stage) plus:
//   - ONE __syncthreads per chunk: wait -> sync -> refill slot((k-1)%3) with
//     chunk k+2 -> compute chunk k. The single barrier proves all warps are
//     done reading chunk k-1, so its slot is safe to overwrite.
//   - conv_a + conv_bt merged into one launch (blockIdx-range dispatch).

#define GM 8192
#define GN 2048
#define GK 2048

#define BM 128
#define BN 128
#define BK 64
#define NTHREADS 256
#define NCHUNK (GK / BK)   // 32

// ---------------- scratch (fp16 operands) ----------------
__device__ __half g_Ah[(size_t)GM * GK];
__device__ __half g_Bh[(size_t)GN * GK];   // W^T, K-major rows

// ---------------- smem stage layout ----------------
// per stage: Ah 16K | Bh 16K   (rows of 128B, SW128)
#define SA 0
#define SB 16384
#define STAGE_BYTES 32768
#define NSTAGE 3
#define SMEM_TOTAL (NSTAGE * STAGE_BYTES)   // 98304/CTA; x2 CTAs = 192KB/SM

#define SWZ(o) ((o) ^ (((o) >> 3) & 0x70))

__device__ __forceinline__ uint32_t smem_u32(const void* p) {
    uint32_t a;
    asm("{ .reg .u64 t; cvta.to.shared.u64 t, %1; cvt.u32.u64 %0, t; }" : "=r"(a) : "l"(p));
    return a;
}
__device__ __forceinline__ void cp16(uint32_t dst, const void* src) {
    asm volatile("cp.async.cg.shared.global [%0], [%1], 16;" :: "r"(dst), "l"(src));
}
__device__ __forceinline__ void cp_commit() {
    asm volatile("cp.async.commit_group;" ::: "memory");
}
__device__ __forceinline__ void cp_wait1() {
    asm volatile("cp.async.wait_group 1;" ::: "memory");
}
__device__ __forceinline__ void ldsm4(uint32_t addr, uint32_t& r0, uint32_t& r1,
                                      uint32_t& r2, uint32_t& r3) {
    asm volatile("ldmatrix.sync.aligned.m8n8.x4.shared.b16 {%0,%1,%2,%3}, [%4];"
                 : "=r"(r0), "=r"(r1), "=r"(r2), "=r"(r3) : "r"(addr));
}
__device__ __forceinline__ void mma16816(float& d0, float& d1, float& d2, float& d3,
                                         uint32_t a0, uint32_t a1, uint32_t a2, uint32_t a3,
                                         uint32_t b0, uint32_t b1) {
    asm volatile(
        "mma.sync.aligned.m16n8k16.row.col.f32.f16.f16.f32 "
        "{%0,%1,%2,%3}, {%4,%5,%6,%7}, {%8,%9}, {%0,%1,%2,%3};"
        : "+f"(d0), "+f"(d1), "+f"(d2), "+f"(d3)
        : "r"(a0), "r"(a1), "r"(a2), "r"(a3), "r"(b0), "r"(b1));
}
__device__ __forceinline__ float elu_f(float x) { return x > 0.0f ? x : expm1f(x); }

// ---------------- merged conversion kernel ----------------
// blocks [0, 4096): A fp32 -> fp16 (16 floats per thread)
// blocks [4096, 8192): W fp32 -> W^T fp16 via smem transpose (32x32 tile)
#define CONV_A_BLOCKS 4096
__global__ __launch_bounds__(256) void conv_kernel(const float* __restrict__ A,
                                                   const float* __restrict__ B) {
    __shared__ float tile[32][33];
    int bid = blockIdx.x;
    int tid = threadIdx.x;
    if (bid < CONV_A_BLOCKS) {
        const float4* A4 = reinterpret_cast<const float4*>(A);
        size_t base = (size_t)bid * 1024 + tid;
        #pragma unroll
        for (int i = 0; i < 4; i++) {
            size_t idx = base + (size_t)i * 256;
            float4 v = A4[idx];
            __half2* ph = reinterpret_cast<__half2*>(g_Ah + idx * 4);
            ph[0] = __half2(__float2half(v.x), __float2half(v.y));
            ph[1] = __half2(__float2half(v.z), __float2half(v.w));
        }
    } else {
        int b = bid - CONV_A_BLOCKS;          // 0..4095
        int n0 = (b & 63) * 32;               // 64 n-tiles
        int k0 = (b >> 6) * 32;               // 64 k-tiles
        int tx = tid & 31, ty = tid >> 5;     // (32,8) logical
        #pragma unroll
        for (int j = 0; j < 32; j += 8)
            tile[ty + j][tx] = B[(size_t)(k0 + ty + j) * GN + n0 + tx];
        __syncthreads();
        #pragma unroll
        for (int j = 0; j < 32; j += 8) {
            float x = tile[tx][ty + j];
            g_Bh[(size_t)(n0 + ty + j) * GK + k0 + tx] = __float2half(x);
        }
    }
}

// ---------------- stage fill (one BK=64 chunk) ----------------
__device__ __forceinline__ void fill_stage(uint32_t sbase, int m0, int n0, int k0) {
    const int tid = threadIdx.x;
    const char* Ah = (const char*)g_Ah;
    const char* Bh = (const char*)g_Bh;
    // A tile: 128 rows x 128B  (1024 cp16, 4 per thread)
    #pragma unroll
    for (int i = tid; i < 1024; i += NTHREADS) {
        int r = i >> 3, c = i & 7;
        uint32_t off = SWZ((uint32_t)(r * 128 + c * 16));
        size_t go = ((size_t)(m0 + r) * GK + k0) * 2 + c * 16;
        cp16(sbase + SA + off, Ah + go);
    }
    // B tile: 128 rows x 128B  (1024 cp16, 4 per thread)
    #pragma unroll
    for (int i = tid; i < 1024; i += NTHREADS) {
        int r = i >> 3, c = i & 7;
        uint32_t off = SWZ((uint32_t)(r * 128 + c * 16));
        size_t go = ((size_t)(n0 + r) * GK + k0) * 2 + c * 16;
        cp16(sbase + SB + off, Bh + go);
    }
}

// ---------------- main GEMM kernel ----------------
__global__ __launch_bounds__(NTHREADS, 2)
void gat_mma_kernel(float* __restrict__ C) {
    extern __shared__ char smem[];
    uint32_t sb = smem_u32(smem);
    const int tid  = threadIdx.x;
    const int wid  = tid >> 5;
    const int lane = tid & 31;
    const int m0 = blockIdx.y * BM;
    const int n0 = blockIdx.x * BN;
    const int warp_m = wid & 1;    // 2 M-tiles of 64
    const int warp_n = wid >> 1;   // 4 N-tiles of 32

    float acc[4][4][4];
    #pragma unroll
    for (int i = 0; i < 4; i++)
        #pragma unroll
        for (int j = 0; j < 4; j++)
            #pragma unroll
            for (int t = 0; t < 4; t++) acc[i][j][t] = 0.0f;

    // per-lane swizzled address bases:
    // SWZ(row*128 + c) == row*128 + (c ^ ((row&7)<<4))  for c < 128
    const int a_row_l = lane & 15;
    const uint32_t a_kb = (uint32_t)((lane >> 4) << 4);
    const int b_j = lane >> 3;
    const int b_row_l = (lane & 7) + ((b_j >> 1) << 3);
    const uint32_t b_kb = (uint32_t)((b_j & 1) << 4);

    uint32_t baseA[4], xA[4];
    #pragma unroll
    for (int mt = 0; mt < 4; mt++) {
        int row = warp_m * 64 + mt * 16 + a_row_l;
        baseA[mt] = (uint32_t)(row << 7);
        xA[mt]    = (uint32_t)((row & 7) << 4);
    }
    uint32_t baseB[2], xB[2];
    #pragma unroll
    for (int np = 0; np < 2; np++) {
        int row = warp_n * 32 + np * 16 + b_row_l;
        baseB[np] = (uint32_t)(row << 7);
        xB[np]    = (uint32_t)((row & 7) << 4);
    }

    // prologue: fill 3 stages (chunks 0,1,2), one commit group each
    #pragma unroll
    for (int s = 0; s < NSTAGE; s++) {
        fill_stage(sb + (uint32_t)s * STAGE_BYTES, m0, n0, s * BK);
        cp_commit();
    }

    for (int k = 0; k < NCHUNK; k++) {
        cp_wait1();        // chunk k resident (<=1 newer group in flight)
        __syncthreads();   // all warps done reading chunk k-1; its writes visible

        // refill the slot chunk k-1 occupied with chunk k+2 (safe: the barrier
        // above proves every warp finished last iteration's reads of it)
        if (k >= 1) {
            int kc = k + 2;
            if (kc < NCHUNK) {
                uint32_t rs = sb + (uint32_t)(kc % NSTAGE) * STAGE_BYTES;
                fill_stage(rs, m0, n0, kc * BK);
            }
            cp_commit();   // empty group when kc >= NCHUNK keeps accounting
        }

        uint32_t stage = sb + (uint32_t)(k % NSTAGE) * STAGE_BYTES;
        #pragma unroll
        for (int ks = 0; ks < 4; ks++) {
            const uint32_t kb = (uint32_t)(ks * 32);

            // B fragments: 2 ldsm.x4 cover 4 n-tiles (warp's 32 cols)
            uint32_t bh[4][2];
            #pragma unroll
            for (int np = 0; np < 2; np++) {
                uint32_t ad = stage + SB + baseB[np] + ((kb + b_kb) ^ xB[np]);
                uint32_t r0, r1, r2, r3;
                ldsm4(ad, r0, r1, r2, r3);
                bh[np * 2 + 0][0] = r0; bh[np * 2 + 0][1] = r1;
                bh[np * 2 + 1][0] = r2; bh[np * 2 + 1][1] = r3;
            }

            // A fragments double-buffered over mt; 4 MMAs per mt
            uint32_t ah[2][4];
            {
                uint32_t ad = stage + SA + baseA[0] + ((kb + a_kb) ^ xA[0]);
                ldsm4(ad, ah[0][0], ah[0][1], ah[0][2], ah[0][3]);
            }
            #pragma unroll
            for (int mt = 0; mt < 4; mt++) {
                const int cb = mt & 1;
                if (mt < 3) {
                    const int nb = (mt + 1) & 1;
                    uint32_t ad = stage + SA + baseA[mt + 1] + ((kb + a_kb) ^ xA[mt + 1]);
                    ldsm4(ad, ah[nb][0], ah[nb][1], ah[nb][2], ah[nb][3]);
                }
                #pragma unroll
                for (int nt = 0; nt < 4; nt++)
                    mma16816(acc[mt][nt][0], acc[mt][nt][1], acc[mt][nt][2], acc[mt][nt][3],
                             ah[cb][0], ah[cb][1], ah[cb][2], ah[cb][3],
                             bh[nt][0], bh[nt][1]);
            }
        }
    }

    // ---------------- epilogue: fused elu, float2 stores ----------------
    const int gp  = lane >> 2;
    const int tg2 = (lane & 3) * 2;
    #pragma unroll
    for (int mt = 0; mt < 4; mt++) {
        int mrow = m0 + warp_m * 64 + mt * 16 + gp;
        #pragma unroll
        for (int nt = 0; nt < 4; nt++) {
            int ncol = n0 + warp_n * 32 + nt * 8 + tg2;
            float2 v0, v1;
            v0.x = elu_f(acc[mt][nt][0]);
            v0.y = elu_f(acc[mt][nt][1]);
            v1.x = elu_f(acc[mt][nt][2]);
            v1.y = elu_f(acc[mt][nt][3]);
            *reinterpret_cast<float2*>(C + (size_t)mrow * GN + ncol) = v0;
            *reinterpret_cast<float2*>(C + (size_t)(mrow + 8) * GN + ncol) = v1;
        }
    }
}

// ---------------- launch ----------------
extern "C" void kernel_launch(void* const* d_in, const int* in_sizes, int n_in,
                              void* d_out, int out_size) {
    const float* input = (const float*)d_in[0];   // [8192, 2048]
    const float* W     = (const float*)d_in[2];   // [2048, 2048]
    float*       out   = (float*)d_out;

    cudaFuncSetAttribute(gat_mma_kernel,
                         cudaFuncAttributeMaxDynamicSharedMemorySize, SMEM_TOTAL);

    conv_kernel<<<CONV_A_BLOCKS + 4096, 256>>>(input, W);
    gat_mma_kernel<<<dim3(GN / BN, GM / BM), NTHREADS, SMEM_TOTAL>>>(out);
}